// round 14
// baseline (speedup 1.0000x reference)
#include <cuda_runtime.h>

// Problem dims (fixed by the dataset)
#define T_STEPS 20
#define BATCH   512
#define DIN     4096
#define HDIM    1024
#define CDIM    100
#define MROWS   (T_STEPS * BATCH)   // 10240
#define KSPLIT  4
#define KCHUNK  (DIN / KSPLIT)      // 1024
#define HELEMS  ((size_t)MROWS * HDIM)   // 10,485,760
#define BK      32

// -------- scratch (static __device__ globals; no runtime allocation) --------
__device__ float g_Hp[KSPLIT * HELEMS];          // split-K partials (160 MB)
__device__ float g_H[HELEMS];                    // merged fc1 outputs (40 MB)
__device__ float g_mean[T_STEPS * HDIM];
__device__ float g_istd[T_STEPS * HDIM];
__device__ float g_S[BATCH * HDIM];              // spike counts
__device__ float g_W2T[HDIM * 128];              // W2 transposed, padded to 128 cols

// ============================================================================
// Kernel 1: split-K partials of C[10240,1024] = A * W1^T   (fp32, FFMA2)
// Tile 128x128, BK=32 (was 16: halves __syncthreads count), 256 threads,
// 8x8 per thread, split-K=4, XOR bank swizzle col^((row&12)<<1) on both tiles.
// 64KB dynamic smem (2 x double-buffered 32KB tiles), occupancy 2.
// Per-output k-order identical to R13 -> bit-identical results.
// ============================================================================
__device__ __forceinline__ void sts_quad(
    float* S, int row, int lmx, const float4& v)
{
    // S points at tile base (layout [BK][128]); same swizzle mask for the
    // whole quad since (row+i)&12 == row&12 for i<4, row in {0,4,8,12,16,...}.
    S[(row + 0) * 128 + lmx] = v.x;
    S[(row + 1) * 128 + lmx] = v.y;
    S[(row + 2) * 128 + lmx] = v.z;
    S[(row + 3) * 128 + lmx] = v.w;
}

__global__ __launch_bounds__(256, 2)
void gemm1_kernel(const float* __restrict__ A, const float* __restrict__ W1)
{
    extern __shared__ __align__(16) float smem[];
    // layout: As[2][BK][128] then Bs[2][BK][128]
    float* Asm = smem;                       // 2*32*128 floats = 32KB
    float* Bsm = smem + 2 * BK * 128;        // 32KB

    const int tid = threadIdx.x;
    const int bm  = blockIdx.y;   // 0..79
    const int bn  = blockIdx.x;   // 0..7
    const int kc  = blockIdx.z;   // 0..3  (K chunk)

    // ---- global->smem loader mapping (coalesced 64B segments per tid-quad) --
    const int lm = tid >> 2;           // 0..63
    const int lk = (tid & 3) << 2;     // 0,4,8,12
    const int lmx = lm ^ (lk << 1);    // swizzled smem column (same for lk+16)

    const float* Ap0 = A  + (size_t)(bm * 128 + lm) * DIN + kc * KCHUNK + lk;
    const float* Ap1 = Ap0 + (size_t)64 * DIN;
    const float* Bp0 = W1 + (size_t)(bn * 128 + lm) * DIN + kc * KCHUNK + lk;
    const float* Bp1 = Bp0 + (size_t)64 * DIN;

    // ---- compute mapping: warp = 32m x 64n subtile; thread = 8m x (4+4)n ----
    const int warp = tid >> 5;
    const int lane = tid & 31;
    const int m0 = (warp >> 1) * 32 + (lane >> 3) * 8;   // mult of 8
    const int n0 = (warp & 1) * 64 + (lane & 7) * 4;     // mult of 4

    const unsigned bs_base = (unsigned)__cvta_generic_to_shared(Bsm);

    unsigned long long acc[8][4];
#pragma unroll
    for (int i = 0; i < 8; i++)
#pragma unroll
        for (int j = 0; j < 4; j++) acc[i][j] = 0ull;

    // prologue: tile 0  (k-quads lk and lk+16, rows lm and lm+64)
    float4 ar0 = *(const float4*)Ap0;
    float4 ar1 = *(const float4*)Ap1;
    float4 ar2 = *(const float4*)(Ap0 + 16);
    float4 ar3 = *(const float4*)(Ap1 + 16);
    float4 br0 = *(const float4*)Bp0;
    float4 br1 = *(const float4*)Bp1;
    float4 br2 = *(const float4*)(Bp0 + 16);
    float4 br3 = *(const float4*)(Bp1 + 16);
    {
        float* Ab = Asm;  float* Bb = Bsm;
        sts_quad(Ab, lk,      lmx,      ar0);
        sts_quad(Ab, lk,      lmx + 64, ar1);
        sts_quad(Ab, lk + 16, lmx,      ar2);
        sts_quad(Ab, lk + 16, lmx + 64, ar3);
        sts_quad(Bb, lk,      lmx,      br0);
        sts_quad(Bb, lk,      lmx + 64, br1);
        sts_quad(Bb, lk + 16, lmx,      br2);
        sts_quad(Bb, lk + 16, lmx + 64, br3);
    }
    __syncthreads();

    const int KT = KCHUNK / BK;   // 32
    int buf = 0;
    for (int kt = 0; kt < KT; kt++) {
        if (kt + 1 < KT) {
            Ap0 += BK; Ap1 += BK; Bp0 += BK; Bp1 += BK;
            ar0 = *(const float4*)Ap0;
            ar1 = *(const float4*)Ap1;
            ar2 = *(const float4*)(Ap0 + 16);
            ar3 = *(const float4*)(Ap1 + 16);
            br0 = *(const float4*)Bp0;
            br1 = *(const float4*)Bp1;
            br2 = *(const float4*)(Bp0 + 16);
            br3 = *(const float4*)(Bp1 + 16);
        }

        const float* Asb = Asm + buf * BK * 128;
        const unsigned bbuf = bs_base + (unsigned)(buf * BK * 128 * 4);
#pragma unroll
        for (int k = 0; k < BK; k++) {
            const int sw = (k & 12) << 1;                 // compile-time per k
            const float4 a0 = *(const float4*)(Asb + k * 128 + (m0 ^ sw));
            const float4 a1 = *(const float4*)(Asb + k * 128 + (m0 ^ sw) + 4);
            unsigned long long bp0, bp1, bp2, bp3;
            const unsigned addr = bbuf + (unsigned)((k * 128 + (n0 ^ sw)) * 4);
            asm("ld.shared.v2.b64 {%0, %1}, [%2];"
                : "=l"(bp0), "=l"(bp1) : "r"(addr));
            asm("ld.shared.v2.b64 {%0, %1}, [%2];"
                : "=l"(bp2), "=l"(bp3) : "r"(addr + 128));

            const float av[8] = {a0.x, a0.y, a0.z, a0.w, a1.x, a1.y, a1.z, a1.w};
#pragma unroll
            for (int i = 0; i < 8; i++) {
                unsigned long long ad;
                asm("mov.b64 %0, {%1, %1};"
                    : "=l"(ad) : "r"(__float_as_uint(av[i])));
                asm("fma.rn.f32x2 %0, %1, %2, %0;" : "+l"(acc[i][0]) : "l"(ad), "l"(bp0));
                asm("fma.rn.f32x2 %0, %1, %2, %0;" : "+l"(acc[i][1]) : "l"(ad), "l"(bp1));
                asm("fma.rn.f32x2 %0, %1, %2, %0;" : "+l"(acc[i][2]) : "l"(ad), "l"(bp2));
                asm("fma.rn.f32x2 %0, %1, %2, %0;" : "+l"(acc[i][3]) : "l"(ad), "l"(bp3));
            }
        }

        if (kt + 1 < KT) {
            float* Ab = Asm + (buf ^ 1) * BK * 128;
            float* Bb = Bsm + (buf ^ 1) * BK * 128;
            sts_quad(Ab, lk,      lmx,      ar0);
            sts_quad(Ab, lk,      lmx + 64, ar1);
            sts_quad(Ab, lk + 16, lmx,      ar2);
            sts_quad(Ab, lk + 16, lmx + 64, ar3);
            sts_quad(Bb, lk,      lmx,      br0);
            sts_quad(Bb, lk,      lmx + 64, br1);
            sts_quad(Bb, lk + 16, lmx,      br2);
            sts_quad(Bb, lk + 16, lmx + 64, br3);
        }
        __syncthreads();
        buf ^= 1;
    }

    // epilogue: store accumulator pairs into this chunk's partial plane
    float* Hp = g_Hp + (size_t)kc * HELEMS;
#pragma unroll
    for (int i = 0; i < 8; i++) {
        float* r = Hp + (size_t)(bm * 128 + m0 + i) * HDIM + bn * 128 + n0;
        *(unsigned long long*)(r)      = acc[i][0];
        *(unsigned long long*)(r + 2)  = acc[i][1];
        *(unsigned long long*)(r + 32) = acc[i][2];
        *(unsigned long long*)(r + 34) = acc[i][3];
    }
}

// ============================================================================
// Kernel 1b: deterministic split-K merge: g_H = ((p0+p1)+p2)+p3  (unchanged)
// ============================================================================
__global__ void merge_kernel()
{
    const size_t i = ((size_t)blockIdx.x * 256 + threadIdx.x) * 4;
    const float4 p0 = *(const float4*)(g_Hp + i);
    const float4 p1 = *(const float4*)(g_Hp + HELEMS + i);
    const float4 p2 = *(const float4*)(g_Hp + 2 * HELEMS + i);
    const float4 p3 = *(const float4*)(g_Hp + 3 * HELEMS + i);
    float4 s;
    s.x = ((p0.x + p1.x) + p2.x) + p3.x;
    s.y = ((p0.y + p1.y) + p2.y) + p3.y;
    s.z = ((p0.z + p1.z) + p2.z) + p3.z;
    s.w = ((p0.w + p1.w) + p2.w) + p3.w;
    *(float4*)(g_H + i) = s;
}

// ============================================================================
// Kernel 2: batch-norm stats per (t, j)   (unchanged)
// ============================================================================
__global__ void bn_stats_kernel()
{
    const int t  = blockIdx.y;
    const int j2 = blockIdx.x * 128 + threadIdx.x;   // 0..511 (column pair)
    const float2* col = (const float2*)(g_H + (size_t)t * BATCH * HDIM) + j2;

    float s0 = 0.f, s1 = 0.f, q0 = 0.f, q1 = 0.f;
#pragma unroll 8
    for (int b = 0; b < BATCH; b++) {
        const float2 v = col[b * (HDIM / 2)];
        s0 += v.x;  q0 += v.x * v.x;
        s1 += v.y;  q1 += v.y * v.y;
    }
    const float inv = 1.0f / (float)BATCH;
    const float m0 = s0 * inv, m1 = s1 * inv;
    const int j = j2 * 2;
    g_mean[t * HDIM + j]     = m0;
    g_mean[t * HDIM + j + 1] = m1;
    g_istd[t * HDIM + j]     = rsqrtf(q0 * inv - m0 * m0 + 1e-4f);
    g_istd[t * HDIM + j + 1] = rsqrtf(q1 * inv - m1 * m1 + 1e-4f);
}

// ============================================================================
// Kernel 3: LIF recurrence -> spike counts S[b,j]   (unchanged)
// ============================================================================
__global__ void recurrence_kernel(const float* __restrict__ gamma)
{
    const int idx = blockIdx.x * 256 + threadIdx.x;   // b*1024 + j
    const int j = idx & (HDIM - 1);

    float mem = 0.f;
    float cnt = 0.f;
#pragma unroll
    for (int t = 0; t < T_STEPS; t++) {
        const float h  = g_H[(size_t)t * (BATCH * HDIM) + idx];
        const float hn = gamma[t * HDIM + j] * (h - g_mean[t * HDIM + j]) *
                         g_istd[t * HDIM + j];
        mem = 0.95f * mem + hn;
        if (mem > 1.0f) { cnt += 1.0f; mem -= 1.0f; }
    }
    g_S[idx] = cnt;
}

// ============================================================================
// Kernel 4a: transpose W2 [100,1024] -> W2T [1024,128]   (unchanged)
// ============================================================================
__global__ void transposeW2_kernel(const float* __restrict__ W2)
{
    const int idx = blockIdx.x * 256 + threadIdx.x;   // 0..131071
    const int k = idx >> 7;
    const int c = idx & 127;
    g_W2T[idx] = (c < CDIM) ? W2[c * HDIM + k] : 0.0f;
}

// ============================================================================
// Kernel 4b: out[b,c] = (1/T) * sum_k S[b,k] * W2T[k,c]   (unchanged)
// ============================================================================
__global__ void out_gemm_kernel(float* __restrict__ out)
{
    __shared__ float sS[8][HDIM];
    const int bb  = blockIdx.x;       // 0..63
    const int tid = threadIdx.x;

    for (int i = tid; i < 8 * HDIM; i += 256) {
        const int r = i >> 10, c = i & (HDIM - 1);
        sS[r][c] = g_S[(bb * 8 + r) * HDIM + c];
    }
    __syncthreads();

    const int br = tid >> 5;   // 0..7
    const int cq = tid & 31;   // 0..31 (25 active -> 100 cols)

    float4 acc = make_float4(0.f, 0.f, 0.f, 0.f);
#pragma unroll 8
    for (int k = 0; k < HDIM; k++) {
        const float  s = sS[br][k];                                 // broadcast
        const float4 w = *(const float4*)&g_W2T[k * 128 + cq * 4];  // coalesced
        acc.x += s * w.x;  acc.y += s * w.y;
        acc.z += s * w.z;  acc.w += s * w.w;
    }
    if (cq < 25) {
        const float sc = 1.0f / (float)T_STEPS;
        float4 o = make_float4(acc.x * sc, acc.y * sc, acc.z * sc, acc.w * sc);
        *(float4*)&out[(bb * 8 + br) * CDIM + cq * 4] = o;
    }
}

// ============================================================================
// launch
// ============================================================================
#define GEMM_SMEM (2 * 2 * BK * 128 * 4)   // 65536 bytes

extern "C" void kernel_launch(void* const* d_in, const int* in_sizes, int n_in,
                              void* d_out, int out_size)
{
    const float* z     = (const float*)d_in[0];   // [20,512,4096]
    const float* W1    = (const float*)d_in[1];   // [1024,4096]
    const float* gamma = (const float*)d_in[2];   // [20,1024]
    const float* W2    = (const float*)d_in[3];   // [100,1024]
    float* out = (float*)d_out;                   // [512,100]

    // idempotent attribute set (dynamic smem > 48KB); not a stream op, capture-safe
    cudaFuncSetAttribute(gemm1_kernel,
                         cudaFuncAttributeMaxDynamicSharedMemorySize, GEMM_SMEM);

    gemm1_kernel<<<dim3(8, 80, KSPLIT), 256, GEMM_SMEM>>>(z, W1);
    merge_kernel<<<(unsigned)(HELEMS / 4 / 256), 256>>>();
    bn_stats_kernel<<<dim3(4, 20), 128>>>();
    recurrence_kernel<<<(BATCH * HDIM) / 256, 256>>>(gamma);
    transposeW2_kernel<<<(HDIM * 128) / 256, 256>>>(W2);
    out_gemm_kernel<<<BATCH / 8, 256>>>(out);
}